// round 1
// baseline (speedup 1.0000x reference)
#include <cuda_runtime.h>
#include <cuda_bf16.h>
#include <math.h>

// Problem constants
#define L 2048
#define S 2048
#define E 2048
#define H 16
#define D 128   // head dim
#define SCALE 0.08838834764831843f  // 1/sqrt(128)

// ---------------- scratch (static device globals; no allocation) -------------
__device__ float g_Q[(long)L * E];
__device__ float g_K[(long)S * E];
__device__ float g_V[(long)S * E];
__device__ float g_tb[H * S];
__device__ float g_scores[(long)H * L * S];   // 256 MB, reused in-place by softmax
__device__ float g_ctx[(long)L * E];
__device__ float g_x[(long)L * E];

// ---------------- reductions -------------------------------------------------
__device__ __forceinline__ float warpReduceSum(float v) {
    #pragma unroll
    for (int o = 16; o > 0; o >>= 1) v += __shfl_xor_sync(0xffffffffu, v, o);
    return v;
}
__device__ __forceinline__ float warpReduceMax(float v) {
    #pragma unroll
    for (int o = 16; o > 0; o >>= 1) v = fmaxf(v, __shfl_xor_sync(0xffffffffu, v, o));
    return v;
}

template<bool MAX>
__device__ __forceinline__ float blockReduce256(float v) {
    __shared__ float sh[8];
    int lane = threadIdx.x & 31, wid = threadIdx.x >> 5;
    v = MAX ? warpReduceMax(v) : warpReduceSum(v);
    if (lane == 0) sh[wid] = v;
    __syncthreads();
    if (wid == 0) {
        float t = (lane < 8) ? sh[lane] : (MAX ? -INFINITY : 0.0f);
        t = MAX ? warpReduceMax(t) : warpReduceSum(t);
        if (lane == 0) sh[0] = t;
    }
    __syncthreads();
    float r = sh[0];
    __syncthreads();  // allow safe reuse of sh by a later call
    return r;
}

// ---------------- NT SGEMM: C[m,n] = scale*sum_k A[m,k]*B[n,k] + bias[n] + res[m,n]
// 128x128 tile, BK=8, 256 threads, 8x8 microtile. All dims assumed divisible.
#define BM 128
#define BN 128
#define BK 8

__global__ __launch_bounds__(256) void sgemm_nt(
    const float* __restrict__ A, const float* __restrict__ B,
    float* __restrict__ C,
    int K, int lda, int ldb, int ldc,
    long aZ, long bZ, long cZ,
    const float* __restrict__ bias, int biasZ,
    const float* __restrict__ res, int ldr,
    float scale)
{
    int z = blockIdx.z;
    A += (long)z * aZ;
    B += (long)z * bZ;
    C += (long)z * cZ;
    if (bias) bias += (long)z * biasZ;

    __shared__ float As[BK][BM];
    __shared__ float Bs[BK][BN];

    int tid = threadIdx.x;
    int tx = tid & 15, ty = tid >> 4;
    int rowA = tid >> 1;          // 0..127
    int k4   = (tid & 1) * 4;     // 0 or 4

    const float* Aptr = A + ((long)(blockIdx.y * BM + rowA)) * lda + k4;
    const float* Bptr = B + ((long)(blockIdx.x * BN + rowA)) * ldb + k4;

    int m0 = ty * 4, m1 = 64 + ty * 4;
    int n0 = tx * 4, n1 = 64 + tx * 4;

    float acc[8][8];
    #pragma unroll
    for (int i = 0; i < 8; i++)
        #pragma unroll
        for (int j = 0; j < 8; j++) acc[i][j] = 0.0f;

    for (int k0 = 0; k0 < K; k0 += BK) {
        float4 a4 = *(const float4*)(Aptr + k0);
        float4 b4 = *(const float4*)(Bptr + k0);
        __syncthreads();
        As[k4+0][rowA] = a4.x; As[k4+1][rowA] = a4.y;
        As[k4+2][rowA] = a4.z; As[k4+3][rowA] = a4.w;
        Bs[k4+0][rowA] = b4.x; Bs[k4+1][rowA] = b4.y;
        Bs[k4+2][rowA] = b4.z; Bs[k4+3][rowA] = b4.w;
        __syncthreads();
        #pragma unroll
        for (int kk = 0; kk < BK; kk++) {
            float4 aA = *(const float4*)&As[kk][m0];
            float4 aB = *(const float4*)&As[kk][m1];
            float4 bA = *(const float4*)&Bs[kk][n0];
            float4 bB = *(const float4*)&Bs[kk][n1];
            float am[8] = {aA.x, aA.y, aA.z, aA.w, aB.x, aB.y, aB.z, aB.w};
            float bn[8] = {bA.x, bA.y, bA.z, bA.w, bB.x, bB.y, bB.z, bB.w};
            #pragma unroll
            for (int i = 0; i < 8; i++)
                #pragma unroll
                for (int j = 0; j < 8; j++)
                    acc[i][j] = fmaf(am[i], bn[j], acc[i][j]);
        }
    }

    #pragma unroll
    for (int i = 0; i < 8; i++) {
        int mm = (i < 4) ? (m0 + i) : (m1 + i - 4);
        long grow = blockIdx.y * BM + mm;
        #pragma unroll
        for (int j = 0; j < 8; j++) {
            int nn = (j < 4) ? (n0 + j) : (n1 + j - 4);
            long gcol = blockIdx.x * BN + nn;
            float v = acc[i][j] * scale;
            if (bias) v += bias[gcol];
            if (res)  v += res[grow * ldr + gcol];
            C[grow * ldc + gcol] = v;
        }
    }
}

// ---------------- NN SGEMM: C[m,n] = sum_k A[m,k]*B[k,n] -------------------
__global__ __launch_bounds__(256) void sgemm_nn(
    const float* __restrict__ A, const float* __restrict__ B,
    float* __restrict__ C,
    int K, int lda, int ldb, int ldc,
    long aZ, long bZ, long cZ)
{
    int z = blockIdx.z;
    A += (long)z * aZ;
    B += (long)z * bZ;
    C += (long)z * cZ;

    __shared__ float As[BK][BM];
    __shared__ float Bs[BK][BN];

    int tid = threadIdx.x;
    int tx = tid & 15, ty = tid >> 4;
    int rowA = tid >> 1;
    int k4   = (tid & 1) * 4;
    int rowB = tid >> 5;           // 0..7
    int colB = (tid & 31) * 4;     // 0..124

    const float* Aptr = A + ((long)(blockIdx.y * BM + rowA)) * lda + k4;
    const float* Bbase = B + (long)blockIdx.x * BN + colB;

    int m0 = ty * 4, m1 = 64 + ty * 4;
    int n0 = tx * 4, n1 = 64 + tx * 4;

    float acc[8][8];
    #pragma unroll
    for (int i = 0; i < 8; i++)
        #pragma unroll
        for (int j = 0; j < 8; j++) acc[i][j] = 0.0f;

    for (int k0 = 0; k0 < K; k0 += BK) {
        float4 a4 = *(const float4*)(Aptr + k0);
        float4 b4 = *(const float4*)(Bbase + (long)(k0 + rowB) * ldb);
        __syncthreads();
        As[k4+0][rowA] = a4.x; As[k4+1][rowA] = a4.y;
        As[k4+2][rowA] = a4.z; As[k4+3][rowA] = a4.w;
        *(float4*)&Bs[rowB][colB] = b4;
        __syncthreads();
        #pragma unroll
        for (int kk = 0; kk < BK; kk++) {
            float4 aA = *(const float4*)&As[kk][m0];
            float4 aB = *(const float4*)&As[kk][m1];
            float4 bA = *(const float4*)&Bs[kk][n0];
            float4 bB = *(const float4*)&Bs[kk][n1];
            float am[8] = {aA.x, aA.y, aA.z, aA.w, aB.x, aB.y, aB.z, aB.w};
            float bn[8] = {bA.x, bA.y, bA.z, bA.w, bB.x, bB.y, bB.z, bB.w};
            #pragma unroll
            for (int i = 0; i < 8; i++)
                #pragma unroll
                for (int j = 0; j < 8; j++)
                    acc[i][j] = fmaf(am[i], bn[j], acc[i][j]);
        }
    }

    #pragma unroll
    for (int i = 0; i < 8; i++) {
        int mm = (i < 4) ? (m0 + i) : (m1 + i - 4);
        long grow = blockIdx.y * BM + mm;
        #pragma unroll
        for (int j = 0; j < 8; j++) {
            int nn = (j < 4) ? (n0 + j) : (n1 + j - 4);
            long gcol = blockIdx.x * BN + nn;
            C[grow * ldc + gcol] = acc[i][j];
        }
    }
}

// ---------------- time bias: tb[h][s] = time_emb[s,:] . tp_w[h,:] + tp_b[h] --
__global__ __launch_bounds__(512) void time_bias_kernel(
    const float* __restrict__ te, const float* __restrict__ tpw,
    const float* __restrict__ tpb, float* __restrict__ tb)
{
    int s = blockIdx.x;
    int w = threadIdx.x >> 5, lane = threadIdx.x & 31;
    const float4* r    = (const float4*)(te  + (long)s * E);
    const float4* wrow = (const float4*)(tpw + (long)w * E);
    float acc = 0.0f;
    for (int e = lane; e < E / 4; e += 32) {
        float4 a = r[e], b = wrow[e];
        acc += a.x * b.x + a.y * b.y + a.z * b.z + a.w * b.w;
    }
    acc = warpReduceSum(acc);
    if (lane == 0) tb[w * S + s] = acc + tpb[w];
}

// ---------------- softmax over rows of length S ------------------------------
__global__ __launch_bounds__(256) void softmax_rows(float* __restrict__ sc)
{
    float* p = sc + (long)blockIdx.x * S;
    int tid = threadIdx.x;
    float vals[8];
    float mx = -INFINITY;
    #pragma unroll
    for (int i = 0; i < 8; i++) {
        vals[i] = p[tid + i * 256];
        mx = fmaxf(mx, vals[i]);
    }
    mx = blockReduce256<true>(mx);
    float sum = 0.0f;
    #pragma unroll
    for (int i = 0; i < 8; i++) {
        vals[i] = __expf(vals[i] - mx);
        sum += vals[i];
    }
    sum = blockReduce256<false>(sum);
    float inv = 1.0f / sum;
    #pragma unroll
    for (int i = 0; i < 8; i++) p[tid + i * 256] = vals[i] * inv;
}

// ---------------- LayerNorm over rows of length E ----------------------------
__global__ __launch_bounds__(256) void layernorm_kernel(
    const float* __restrict__ x, const float* __restrict__ g,
    const float* __restrict__ b, float* __restrict__ out)
{
    const float* xr = x + (long)blockIdx.x * E;
    float*       yr = out + (long)blockIdx.x * E;
    int tid = threadIdx.x;
    float vals[8];
    float s = 0.0f, s2 = 0.0f;
    #pragma unroll
    for (int i = 0; i < 8; i++) {
        float v = xr[tid + i * 256];
        vals[i] = v;
        s += v;
        s2 += v * v;
    }
    s  = blockReduce256<false>(s);
    s2 = blockReduce256<false>(s2);
    float mean = s * (1.0f / E);
    float var  = s2 * (1.0f / E) - mean * mean;
    float rstd = rsqrtf(var + 1e-5f);
    #pragma unroll
    for (int i = 0; i < 8; i++) {
        int c = tid + i * 256;
        yr[c] = (vals[i] - mean) * rstd * g[c] + b[c];
    }
}

// ---------------- launch -----------------------------------------------------
extern "C" void kernel_launch(void* const* d_in, const int* in_sizes, int n_in,
                              void* d_out, int out_size)
{
    const float* query    = (const float*)d_in[0];
    const float* key      = (const float*)d_in[1];
    const float* value    = (const float*)d_in[2];
    const float* time_emb = (const float*)d_in[3];
    const float* in_w     = (const float*)d_in[4];
    const float* in_b     = (const float*)d_in[5];
    const float* out_w    = (const float*)d_in[6];
    const float* out_b    = (const float*)d_in[7];
    const float* tp_w     = (const float*)d_in[8];
    const float* tp_b     = (const float*)d_in[9];
    const float* ln_g     = (const float*)d_in[10];
    const float* ln_b     = (const float*)d_in[11];

    float *Q, *K, *V, *tb, *sc, *ctx, *x;
    cudaGetSymbolAddress((void**)&Q,   g_Q);
    cudaGetSymbolAddress((void**)&K,   g_K);
    cudaGetSymbolAddress((void**)&V,   g_V);
    cudaGetSymbolAddress((void**)&tb,  g_tb);
    cudaGetSymbolAddress((void**)&sc,  g_scores);
    cudaGetSymbolAddress((void**)&ctx, g_ctx);
    cudaGetSymbolAddress((void**)&x,   g_x);

    // 1. time bias (H x S)
    time_bias_kernel<<<S, 512>>>(time_emb, tp_w, tp_b, tb);

    // 2. Q, K, V projections: (2048x2048) = X @ W^T + b
    dim3 g16(E / BN, L / BM, 1);
    sgemm_nt<<<g16, 256>>>(query, in_w,             Q, E, E, E, E, 0, 0, 0,
                           in_b,         0, nullptr, 0, 1.0f);
    sgemm_nt<<<g16, 256>>>(key,   in_w + (long)E*E, K, E, E, E, E, 0, 0, 0,
                           in_b + E,     0, nullptr, 0, 1.0f);
    sgemm_nt<<<g16, 256>>>(value, in_w + 2L*E*E,    V, E, E, E, E, 0, 0, 0,
                           in_b + 2*E,   0, nullptr, 0, 1.0f);

    // 3. scores[h] = scale * Q_h K_h^T + tb[h]   (grid.z = heads)
    dim3 gsc(S / BN, L / BM, H);
    sgemm_nt<<<gsc, 256>>>(Q, K, sc, D, E, E, S,
                           /*aZ*/ D, /*bZ*/ D, /*cZ*/ (long)L * S,
                           tb, S, nullptr, 0, SCALE);

    // 4. softmax rows
    softmax_rows<<<H * L, 256>>>(sc);

    // 5. ctx[h] = P_h @ V_h   (M=L, N=D, K=S)
    dim3 gctx(D / BN, L / BM, H);
    sgemm_nn<<<gctx, 256>>>(sc, V, ctx, S, S, E, E,
                            /*aZ*/ (long)L * S, /*bZ*/ D, /*cZ*/ D);

    // 6. out projection + residual: x = ctx @ out_w^T + out_b + query
    sgemm_nt<<<g16, 256>>>(ctx, out_w, x, E, E, E, E, 0, 0, 0,
                           out_b, 0, query, E, 1.0f);

    // 7. LayerNorm -> d_out
    layernorm_kernel<<<L, 256>>>(x, ln_g, ln_b, (float*)d_out);
}

// round 2
// speedup vs baseline: 2.0178x; 2.0178x over previous
#include <cuda_runtime.h>
#include <cuda_bf16.h>
#include <math.h>
#include <stdint.h>

// Problem constants
#define L 2048
#define S 2048
#define E 2048
#define H 16
#define D 128
#define SCALE 0.08838834764831843f  // 1/sqrt(128)

// ---------------- scratch (static device globals; no allocation) -------------
__device__ float g_Q[(long)L * E];
__device__ float g_K[(long)S * E];
__device__ float g_V[(long)S * E];
__device__ float g_tb[H * S];
__device__ float g_scores[(long)H * L * S];
__device__ float g_ctx[(long)L * E];
__device__ float g_x[(long)L * E];

// ---------------- helpers ----------------------------------------------------
__device__ __forceinline__ uint32_t f2tf32(float f) {
    uint32_t u;
    asm("cvt.rna.tf32.f32 %0, %1;" : "=r"(u) : "f"(f));
    return u;
}

__device__ __forceinline__ void mma_tf32(float c[4],
                                         uint32_t a0, uint32_t a1, uint32_t a2, uint32_t a3,
                                         uint32_t b0, uint32_t b1) {
    asm volatile(
        "mma.sync.aligned.m16n8k8.row.col.f32.tf32.tf32.f32 "
        "{%0,%1,%2,%3}, {%4,%5,%6,%7}, {%8,%9}, {%0,%1,%2,%3};\n"
        : "+f"(c[0]), "+f"(c[1]), "+f"(c[2]), "+f"(c[3])
        : "r"(a0), "r"(a1), "r"(a2), "r"(a3), "r"(b0), "r"(b1));
}

__device__ __forceinline__ float warpReduceSum(float v) {
    #pragma unroll
    for (int o = 16; o > 0; o >>= 1) v += __shfl_xor_sync(0xffffffffu, v, o);
    return v;
}
__device__ __forceinline__ float warpReduceMax(float v) {
    #pragma unroll
    for (int o = 16; o > 0; o >>= 1) v = fmaxf(v, __shfl_xor_sync(0xffffffffu, v, o));
    return v;
}
template<bool MAX>
__device__ __forceinline__ float blockReduce256(float v) {
    __shared__ float sh[8];
    int lane = threadIdx.x & 31, wid = threadIdx.x >> 5;
    v = MAX ? warpReduceMax(v) : warpReduceSum(v);
    if (lane == 0) sh[wid] = v;
    __syncthreads();
    if (wid == 0) {
        float t = (lane < 8) ? sh[lane] : (MAX ? -INFINITY : 0.0f);
        t = MAX ? warpReduceMax(t) : warpReduceSum(t);
        if (lane == 0) sh[0] = t;
    }
    __syncthreads();
    float r = sh[0];
    __syncthreads();
    return r;
}

// ---------------- tensor-core GEMM ------------------------------------------
// C[m,n] = scale * sum_k A[m,k] * B'[n,k] + bias[n] (+res[m,n])
//   BT=true : B'[n,k] = B[n*ldb + k]   (NT)
//   BT=false: B'[n,k] = B[k*ldb + n]   (NN)
// Block tile 128x128, BK=16, 256 threads (8 warps, warp tile 64x32),
// mma.sync m16n8k8 tf32, double-buffered smem (stride 136 -> conflict-free).
#define BM 128
#define BN 128
#define BK 16
#define SMP 136   // padded stride in words

template<bool BT>
__global__ __launch_bounds__(256, 2) void mma_gemm(
    const float* __restrict__ A, const float* __restrict__ B,
    float* __restrict__ C,
    int K, int lda, int ldb, int ldc,
    long aZ, long bZ, long cZ,
    const float* __restrict__ bias, long biasZ,
    const float* __restrict__ res, int ldr,
    float scale)
{
    int z = blockIdx.z;
    A += (long)z * aZ;
    B += (long)z * bZ;
    C += (long)z * cZ;
    if (bias) bias += (long)z * biasZ;

    __shared__ uint32_t As[2][BK][SMP];
    __shared__ uint32_t Bs[2][BK][SMP];

    const int tid = threadIdx.x;
    const int wid = tid >> 5;
    const int lane = tid & 31;
    const int g = lane >> 2;     // 0..7
    const int tig = lane & 3;    // 0..3
    const int wm = (wid & 1) * 64;   // 2 m-warps
    const int wn = (wid >> 1) * 32;  // 4 n-warps

    const long m0g = (long)blockIdx.y * BM;
    const long n0g = (long)blockIdx.x * BN;

    const float* Ab = A + m0g * lda;

    float acc[4][4][4];
    #pragma unroll
    for (int i = 0; i < 4; i++)
        #pragma unroll
        for (int j = 0; j < 4; j++)
            #pragma unroll
            for (int r = 0; r < 4; r++) acc[i][j][r] = 0.0f;

    // ---- global load of one stage into registers ----
    float4 raA[2], raB[2];
    auto ldg_stage = [&](int k0) {
        #pragma unroll
        for (int i = 0; i < 2; i++) {
            int lin = tid * 2 + i;
            int m = lin >> 2;
            int kq = (lin & 3) * 4;
            raA[i] = *(const float4*)(Ab + (long)m * lda + k0 + kq);
        }
        if (BT) {
            const float* Bb = B + n0g * ldb;
            #pragma unroll
            for (int i = 0; i < 2; i++) {
                int lin = tid * 2 + i;
                int n = lin >> 2;
                int kq = (lin & 3) * 4;
                raB[i] = *(const float4*)(Bb + (long)n * ldb + k0 + kq);
            }
        } else {
            #pragma unroll
            for (int i = 0; i < 2; i++) {
                int lin = i * 256 + tid;
                int kk = lin >> 5;
                int n4 = (lin & 31) * 4;
                raB[i] = *(const float4*)(B + (long)(k0 + kk) * ldb + n0g + n4);
            }
        }
    };

    auto sts_stage = [&](int st) {
        #pragma unroll
        for (int i = 0; i < 2; i++) {
            int lin = tid * 2 + i;
            int m = lin >> 2;
            int kq = (lin & 3) * 4;
            As[st][kq + 0][m] = f2tf32(raA[i].x);
            As[st][kq + 1][m] = f2tf32(raA[i].y);
            As[st][kq + 2][m] = f2tf32(raA[i].z);
            As[st][kq + 3][m] = f2tf32(raA[i].w);
        }
        if (BT) {
            #pragma unroll
            for (int i = 0; i < 2; i++) {
                int lin = tid * 2 + i;
                int n = lin >> 2;
                int kq = (lin & 3) * 4;
                Bs[st][kq + 0][n] = f2tf32(raB[i].x);
                Bs[st][kq + 1][n] = f2tf32(raB[i].y);
                Bs[st][kq + 2][n] = f2tf32(raB[i].z);
                Bs[st][kq + 3][n] = f2tf32(raB[i].w);
            }
        } else {
            #pragma unroll
            for (int i = 0; i < 2; i++) {
                int lin = i * 256 + tid;
                int kk = lin >> 5;
                int n4 = (lin & 31) * 4;
                Bs[st][kk][n4 + 0] = f2tf32(raB[i].x);
                Bs[st][kk][n4 + 1] = f2tf32(raB[i].y);
                Bs[st][kk][n4 + 2] = f2tf32(raB[i].z);
                Bs[st][kk][n4 + 3] = f2tf32(raB[i].w);
            }
        }
    };

    auto compute_stage = [&](int st) {
        #pragma unroll
        for (int kk = 0; kk < BK; kk += 8) {
            uint32_t af[4][4];
            #pragma unroll
            for (int mt = 0; mt < 4; mt++) {
                int r0 = wm + mt * 16 + g;
                af[mt][0] = As[st][kk + tig][r0];
                af[mt][1] = As[st][kk + tig][r0 + 8];
                af[mt][2] = As[st][kk + tig + 4][r0];
                af[mt][3] = As[st][kk + tig + 4][r0 + 8];
            }
            uint32_t bf[4][2];
            #pragma unroll
            for (int nt = 0; nt < 4; nt++) {
                int c = wn + nt * 8 + g;
                bf[nt][0] = Bs[st][kk + tig][c];
                bf[nt][1] = Bs[st][kk + tig + 4][c];
            }
            #pragma unroll
            for (int mt = 0; mt < 4; mt++)
                #pragma unroll
                for (int nt = 0; nt < 4; nt++)
                    mma_tf32(acc[mt][nt], af[mt][0], af[mt][1], af[mt][2], af[mt][3],
                             bf[nt][0], bf[nt][1]);
        }
    };

    // ---- pipelined main loop ----
    const int nStages = K / BK;
    ldg_stage(0);
    sts_stage(0);
    __syncthreads();
    for (int it = 0; it < nStages; it++) {
        int st = it & 1;
        if (it + 1 < nStages) ldg_stage((it + 1) * BK);
        compute_stage(st);
        if (it + 1 < nStages) {
            sts_stage(st ^ 1);
            __syncthreads();
        }
    }

    // ---- epilogue ----
    #pragma unroll
    for (int mt = 0; mt < 4; mt++) {
        long r0 = m0g + wm + mt * 16 + g;
        long r1 = r0 + 8;
        #pragma unroll
        for (int nt = 0; nt < 4; nt++) {
            long c = n0g + wn + nt * 8 + 2 * tig;
            float v0 = acc[mt][nt][0] * scale;
            float v1 = acc[mt][nt][1] * scale;
            float v2 = acc[mt][nt][2] * scale;
            float v3 = acc[mt][nt][3] * scale;
            if (bias) {
                float b0 = bias[c], b1 = bias[c + 1];
                v0 += b0; v1 += b1; v2 += b0; v3 += b1;
            }
            if (res) {
                v0 += res[r0 * ldr + c];
                v1 += res[r0 * ldr + c + 1];
                v2 += res[r1 * ldr + c];
                v3 += res[r1 * ldr + c + 1];
            }
            *(float2*)(C + r0 * ldc + c) = make_float2(v0, v1);
            *(float2*)(C + r1 * ldc + c) = make_float2(v2, v3);
        }
    }
}

// ---------------- time bias: tb[h][s] = time_emb[s,:] . tp_w[h,:] + tp_b[h] --
__global__ __launch_bounds__(512) void time_bias_kernel(
    const float* __restrict__ te, const float* __restrict__ tpw,
    const float* __restrict__ tpb, float* __restrict__ tb)
{
    int s = blockIdx.x;
    int w = threadIdx.x >> 5, lane = threadIdx.x & 31;
    const float4* r    = (const float4*)(te  + (long)s * E);
    const float4* wrow = (const float4*)(tpw + (long)w * E);
    float acc = 0.0f;
    for (int e = lane; e < E / 4; e += 32) {
        float4 a = r[e], b = wrow[e];
        acc += a.x * b.x + a.y * b.y + a.z * b.z + a.w * b.w;
    }
    acc = warpReduceSum(acc);
    if (lane == 0) tb[w * S + s] = acc + tpb[w];
}

// ---------------- softmax over rows of length S ------------------------------
__global__ __launch_bounds__(256) void softmax_rows(float* __restrict__ sc)
{
    float* p = sc + (long)blockIdx.x * S;
    int tid = threadIdx.x;
    float vals[8];
    float mx = -INFINITY;
    #pragma unroll
    for (int i = 0; i < 8; i++) {
        vals[i] = p[tid + i * 256];
        mx = fmaxf(mx, vals[i]);
    }
    mx = blockReduce256<true>(mx);
    float sum = 0.0f;
    #pragma unroll
    for (int i = 0; i < 8; i++) {
        vals[i] = __expf(vals[i] - mx);
        sum += vals[i];
    }
    sum = blockReduce256<false>(sum);
    float inv = 1.0f / sum;
    #pragma unroll
    for (int i = 0; i < 8; i++) p[tid + i * 256] = vals[i] * inv;
}

// ---------------- LayerNorm over rows of length E ----------------------------
__global__ __launch_bounds__(256) void layernorm_kernel(
    const float* __restrict__ x, const float* __restrict__ g,
    const float* __restrict__ b, float* __restrict__ out)
{
    const float* xr = x + (long)blockIdx.x * E;
    float*       yr = out + (long)blockIdx.x * E;
    int tid = threadIdx.x;
    float vals[8];
    float s = 0.0f, s2 = 0.0f;
    #pragma unroll
    for (int i = 0; i < 8; i++) {
        float v = xr[tid + i * 256];
        vals[i] = v;
        s += v;
        s2 += v * v;
    }
    s  = blockReduce256<false>(s);
    s2 = blockReduce256<false>(s2);
    float mean = s * (1.0f / E);
    float var  = s2 * (1.0f / E) - mean * mean;
    float rstd = rsqrtf(var + 1e-5f);
    #pragma unroll
    for (int i = 0; i < 8; i++) {
        int c = tid + i * 256;
        yr[c] = (vals[i] - mean) * rstd * g[c] + b[c];
    }
}

// ---------------- launch -----------------------------------------------------
extern "C" void kernel_launch(void* const* d_in, const int* in_sizes, int n_in,
                              void* d_out, int out_size)
{
    const float* query    = (const float*)d_in[0];
    const float* key      = (const float*)d_in[1];
    const float* value    = (const float*)d_in[2];
    const float* time_emb = (const float*)d_in[3];
    const float* in_w     = (const float*)d_in[4];
    const float* in_b     = (const float*)d_in[5];
    const float* out_w    = (const float*)d_in[6];
    const float* out_b    = (const float*)d_in[7];
    const float* tp_w     = (const float*)d_in[8];
    const float* tp_b     = (const float*)d_in[9];
    const float* ln_g     = (const float*)d_in[10];
    const float* ln_b     = (const float*)d_in[11];

    float *Q, *K, *V, *tb, *sc, *ctx, *x;
    cudaGetSymbolAddress((void**)&Q,   g_Q);
    cudaGetSymbolAddress((void**)&K,   g_K);
    cudaGetSymbolAddress((void**)&V,   g_V);
    cudaGetSymbolAddress((void**)&tb,  g_tb);
    cudaGetSymbolAddress((void**)&sc,  g_scores);
    cudaGetSymbolAddress((void**)&ctx, g_ctx);
    cudaGetSymbolAddress((void**)&x,   g_x);

    // 1. time bias (H x S)
    time_bias_kernel<<<S, 512>>>(time_emb, tp_w, tp_b, tb);

    // 2. Q, K, V projections
    dim3 g16(E / BN, L / BM, 1);
    mma_gemm<true><<<g16, 256>>>(query, in_w,             Q, E, E, E, E, 0, 0, 0,
                                 in_b,       0, nullptr, 0, 1.0f);
    mma_gemm<true><<<g16, 256>>>(key,   in_w + (long)E*E, K, E, E, E, E, 0, 0, 0,
                                 in_b + E,   0, nullptr, 0, 1.0f);
    mma_gemm<true><<<g16, 256>>>(value, in_w + 2L*E*E,    V, E, E, E, E, 0, 0, 0,
                                 in_b + 2*E, 0, nullptr, 0, 1.0f);

    // 3. scores[h] = scale * Q_h K_h^T + tb[h]
    dim3 gsc(S / BN, L / BM, H);
    mma_gemm<true><<<gsc, 256>>>(Q, K, sc, D, E, E, S,
                                 (long)D, (long)D, (long)L * S,
                                 tb, (long)S, nullptr, 0, SCALE);

    // 4. softmax rows
    softmax_rows<<<H * L, 256>>>(sc);

    // 5. ctx[h] = P_h @ V_h   (M=L, N=D, K=S), NN
    dim3 gctx(D / BN, L / BM, H);
    mma_gemm<false><<<gctx, 256>>>(sc, V, ctx, S, S, E, E,
                                   (long)L * S, (long)D, (long)D,
                                   nullptr, 0, nullptr, 0, 1.0f);

    // 6. out projection + residual
    mma_gemm<true><<<g16, 256>>>(ctx, out_w, x, E, E, E, E, 0, 0, 0,
                                 out_b, 0, query, E, 1.0f);

    // 7. LayerNorm -> d_out
    layernorm_kernel<<<L, 256>>>(x, ln_g, ln_b, (float*)d_out);
}

// round 3
// speedup vs baseline: 2.6818x; 1.3291x over previous
#include <cuda_runtime.h>
#include <cuda_bf16.h>
#include <math.h>
#include <stdint.h>

// Problem constants
#define L 2048
#define S 2048
#define E 2048
#define H 16
#define D 128
#define SCALE 0.08838834764831843f  // 1/sqrt(128)

// ---------------- scratch (static device globals; no allocation) -------------
__device__ float g_Q[(long)L * E];
__device__ float g_K[(long)S * E];
__device__ float g_V[(long)S * E];
__device__ float g_tb[H * S];
__device__ float g_scores[(long)H * L * S];
__device__ float g_ctx[(long)L * E];
__device__ float g_x[(long)L * E];

// ---------------- helpers ----------------------------------------------------
// pack two fp32 -> bf16x2 (lo = x, hi = y)
__device__ __forceinline__ uint32_t pack_bf16(float x, float y) {
    uint32_t u;
    asm("cvt.rn.bf16x2.f32 %0, %1, %2;" : "=r"(u) : "f"(y), "f"(x));
    return u;
}

__device__ __forceinline__ void mma_bf16(float c[4],
                                         uint32_t a0, uint32_t a1, uint32_t a2, uint32_t a3,
                                         uint32_t b0, uint32_t b1) {
    asm volatile(
        "mma.sync.aligned.m16n8k16.row.col.f32.bf16.bf16.f32 "
        "{%0,%1,%2,%3}, {%4,%5,%6,%7}, {%8,%9}, {%0,%1,%2,%3};\n"
        : "+f"(c[0]), "+f"(c[1]), "+f"(c[2]), "+f"(c[3])
        : "r"(a0), "r"(a1), "r"(a2), "r"(a3), "r"(b0), "r"(b1));
}

__device__ __forceinline__ float warpReduceSum(float v) {
    #pragma unroll
    for (int o = 16; o > 0; o >>= 1) v += __shfl_xor_sync(0xffffffffu, v, o);
    return v;
}
__device__ __forceinline__ float warpReduceMax(float v) {
    #pragma unroll
    for (int o = 16; o > 0; o >>= 1) v = fmaxf(v, __shfl_xor_sync(0xffffffffu, v, o));
    return v;
}
template<bool MAX>
__device__ __forceinline__ float blockReduce256(float v) {
    __shared__ float sh[8];
    int lane = threadIdx.x & 31, wid = threadIdx.x >> 5;
    v = MAX ? warpReduceMax(v) : warpReduceSum(v);
    if (lane == 0) sh[wid] = v;
    __syncthreads();
    if (wid == 0) {
        float t = (lane < 8) ? sh[lane] : (MAX ? -INFINITY : 0.0f);
        t = MAX ? warpReduceMax(t) : warpReduceSum(t);
        if (lane == 0) sh[0] = t;
    }
    __syncthreads();
    float r = sh[0];
    __syncthreads();
    return r;
}

// ---------------- tensor-core GEMM (bf16 mma, fp32 accumulate) ---------------
// C[m,n] = scale * sum_k A[m,k] * B'[n,k] + bias[n] (+res[m,n])
//   BT=true : B'[n,k] = B[n*ldb + k]   (NT)
//   BT=false: B'[n,k] = B[k*ldb + n]   (NN)
// Block tile 128x128, BK=32 (16 bf16x2 k-pairs/stage), 256 threads (8 warps,
// warp tile 64x32), mma m16n8k16, double-buffered smem.
#define BM 128
#define BN 128
#define BK 32
#define KP 16     // k-pairs per stage
#define SMP 136   // padded row stride (words)

template<bool BT>
__global__ __launch_bounds__(256, 2) void mma_gemm(
    const float* __restrict__ A, const float* __restrict__ B,
    float* __restrict__ C,
    int K, int lda, int ldb, int ldc,
    long aZ, long bZ, long cZ,
    const float* __restrict__ bias, long biasZ,
    const float* __restrict__ res, int ldr,
    float scale)
{
    int z = blockIdx.z;
    A += (long)z * aZ;
    B += (long)z * bZ;
    C += (long)z * cZ;
    if (bias) bias += (long)z * biasZ;

    __shared__ uint32_t As[2][KP][SMP];   // [kpair][m], bf16x2 (k even|odd)
    __shared__ uint32_t Bs[2][KP][SMP];   // [kpair][n]

    const int tid = threadIdx.x;
    const int wid = tid >> 5;
    const int lane = tid & 31;
    const int g = lane >> 2;     // 0..7
    const int tig = lane & 3;    // 0..3
    const int wm = (wid & 1) * 64;
    const int wn = (wid >> 1) * 32;

    const long m0g = (long)blockIdx.y * BM;
    const long n0g = (long)blockIdx.x * BN;

    const float* Ab = A + m0g * lda;

    float acc[4][4][4];
    #pragma unroll
    for (int i = 0; i < 4; i++)
        #pragma unroll
        for (int j = 0; j < 4; j++)
            #pragma unroll
            for (int r = 0; r < 4; r++) acc[i][j][r] = 0.0f;

    // per-stage register staging: 16 floats each for A and B
    float4 ra[4], rb[4];
    const int mA = tid >> 1;          // 0..127
    const int qA = (tid & 1) * 16;    // k sub-offset 0/16

    // NN B loader indices
    const int kpB = tid >> 4;         // 0..15
    const int n0B = (tid & 15) * 8;   // 0..120

    auto ldg_stage = [&](int k0) {
        const float* ap = Ab + (long)mA * lda + k0 + qA;
        #pragma unroll
        for (int j = 0; j < 4; j++) ra[j] = *(const float4*)(ap + 4 * j);
        if (BT) {
            const float* bp = B + (n0g + mA) * ldb + k0 + qA;
            #pragma unroll
            for (int j = 0; j < 4; j++) rb[j] = *(const float4*)(bp + 4 * j);
        } else {
            const float* bp0 = B + (long)(k0 + 2 * kpB) * ldb + n0g + n0B;
            const float* bp1 = bp0 + ldb;
            rb[0] = *(const float4*)(bp0);
            rb[1] = *(const float4*)(bp0 + 4);
            rb[2] = *(const float4*)(bp1);
            rb[3] = *(const float4*)(bp1 + 4);
        }
    };

    auto sts_stage = [&](int st) {
        int kp0 = (qA >> 1);   // 0 or 8
        #pragma unroll
        for (int j = 0; j < 4; j++) {
            As[st][kp0 + 2 * j + 0][mA] = pack_bf16(ra[j].x, ra[j].y);
            As[st][kp0 + 2 * j + 1][mA] = pack_bf16(ra[j].z, ra[j].w);
        }
        if (BT) {
            #pragma unroll
            for (int j = 0; j < 4; j++) {
                Bs[st][kp0 + 2 * j + 0][mA] = pack_bf16(rb[j].x, rb[j].y);
                Bs[st][kp0 + 2 * j + 1][mA] = pack_bf16(rb[j].z, rb[j].w);
            }
        } else {
            const float* r0 = (const float*)&rb[0];   // row k even, 8 floats
            const float* r1 = (const float*)&rb[2];   // row k odd, 8 floats
            #pragma unroll
            for (int j = 0; j < 8; j++)
                Bs[st][kpB][n0B + j] = pack_bf16(r0[j], r1[j]);
        }
    };

    auto compute_stage = [&](int st) {
        #pragma unroll
        for (int s = 0; s < 2; s++) {
            const int kb = 8 * s;
            uint32_t af[4][4];
            #pragma unroll
            for (int mt = 0; mt < 4; mt++) {
                int r0 = wm + mt * 16 + g;
                af[mt][0] = As[st][kb + tig][r0];
                af[mt][1] = As[st][kb + tig][r0 + 8];
                af[mt][2] = As[st][kb + tig + 4][r0];
                af[mt][3] = As[st][kb + tig + 4][r0 + 8];
            }
            uint32_t bf[4][2];
            #pragma unroll
            for (int nt = 0; nt < 4; nt++) {
                int c = wn + nt * 8 + g;
                bf[nt][0] = Bs[st][kb + tig][c];
                bf[nt][1] = Bs[st][kb + tig + 4][c];
            }
            #pragma unroll
            for (int mt = 0; mt < 4; mt++)
                #pragma unroll
                for (int nt = 0; nt < 4; nt++)
                    mma_bf16(acc[mt][nt], af[mt][0], af[mt][1], af[mt][2], af[mt][3],
                             bf[nt][0], bf[nt][1]);
        }
    };

    const int nStages = K / BK;
    ldg_stage(0);
    sts_stage(0);
    __syncthreads();
    for (int it = 0; it < nStages; it++) {
        int st = it & 1;
        if (it + 1 < nStages) ldg_stage((it + 1) * BK);
        compute_stage(st);
        if (it + 1 < nStages) {
            sts_stage(st ^ 1);
            __syncthreads();
        }
    }

    // ---- epilogue ----
    #pragma unroll
    for (int mt = 0; mt < 4; mt++) {
        long r0 = m0g + wm + mt * 16 + g;
        long r1 = r0 + 8;
        #pragma unroll
        for (int nt = 0; nt < 4; nt++) {
            long c = n0g + wn + nt * 8 + 2 * tig;
            float v0 = acc[mt][nt][0] * scale;
            float v1 = acc[mt][nt][1] * scale;
            float v2 = acc[mt][nt][2] * scale;
            float v3 = acc[mt][nt][3] * scale;
            if (bias) {
                float b0 = bias[c], b1 = bias[c + 1];
                v0 += b0; v1 += b1; v2 += b0; v3 += b1;
            }
            if (res) {
                v0 += res[r0 * ldr + c];
                v1 += res[r0 * ldr + c + 1];
                v2 += res[r1 * ldr + c];
                v3 += res[r1 * ldr + c + 1];
            }
            *(float2*)(C + r0 * ldc + c) = make_float2(v0, v1);
            *(float2*)(C + r1 * ldc + c) = make_float2(v2, v3);
        }
    }
}

// ---------------- time bias --------------------------------------------------
__global__ __launch_bounds__(512) void time_bias_kernel(
    const float* __restrict__ te, const float* __restrict__ tpw,
    const float* __restrict__ tpb, float* __restrict__ tb)
{
    int s = blockIdx.x;
    int w = threadIdx.x >> 5, lane = threadIdx.x & 31;
    const float4* r    = (const float4*)(te  + (long)s * E);
    const float4* wrow = (const float4*)(tpw + (long)w * E);
    float acc = 0.0f;
    for (int e = lane; e < E / 4; e += 32) {
        float4 a = r[e], b = wrow[e];
        acc += a.x * b.x + a.y * b.y + a.z * b.z + a.w * b.w;
    }
    acc = warpReduceSum(acc);
    if (lane == 0) tb[w * S + s] = acc + tpb[w];
}

// ---------------- softmax ----------------------------------------------------
__global__ __launch_bounds__(256) void softmax_rows(float* __restrict__ sc)
{
    float* p = sc + (long)blockIdx.x * S;
    int tid = threadIdx.x;
    float vals[8];
    float mx = -INFINITY;
    #pragma unroll
    for (int i = 0; i < 8; i++) {
        vals[i] = p[tid + i * 256];
        mx = fmaxf(mx, vals[i]);
    }
    mx = blockReduce256<true>(mx);
    float sum = 0.0f;
    #pragma unroll
    for (int i = 0; i < 8; i++) {
        vals[i] = __expf(vals[i] - mx);
        sum += vals[i];
    }
    sum = blockReduce256<false>(sum);
    float inv = 1.0f / sum;
    #pragma unroll
    for (int i = 0; i < 8; i++) p[tid + i * 256] = vals[i] * inv;
}

// ---------------- LayerNorm --------------------------------------------------
__global__ __launch_bounds__(256) void layernorm_kernel(
    const float* __restrict__ x, const float* __restrict__ g,
    const float* __restrict__ b, float* __restrict__ out)
{
    const float* xr = x + (long)blockIdx.x * E;
    float*       yr = out + (long)blockIdx.x * E;
    int tid = threadIdx.x;
    float vals[8];
    float s = 0.0f, s2 = 0.0f;
    #pragma unroll
    for (int i = 0; i < 8; i++) {
        float v = xr[tid + i * 256];
        vals[i] = v;
        s += v;
        s2 += v * v;
    }
    s  = blockReduce256<false>(s);
    s2 = blockReduce256<false>(s2);
    float mean = s * (1.0f / E);
    float var  = s2 * (1.0f / E) - mean * mean;
    float rstd = rsqrtf(var + 1e-5f);
    #pragma unroll
    for (int i = 0; i < 8; i++) {
        int c = tid + i * 256;
        yr[c] = (vals[i] - mean) * rstd * g[c] + b[c];
    }
}

// ---------------- launch -----------------------------------------------------
extern "C" void kernel_launch(void* const* d_in, const int* in_sizes, int n_in,
                              void* d_out, int out_size)
{
    const float* query    = (const float*)d_in[0];
    const float* key      = (const float*)d_in[1];
    const float* value    = (const float*)d_in[2];
    const float* time_emb = (const float*)d_in[3];
    const float* in_w     = (const float*)d_in[4];
    const float* in_b     = (const float*)d_in[5];
    const float* out_w    = (const float*)d_in[6];
    const float* out_b    = (const float*)d_in[7];
    const float* tp_w     = (const float*)d_in[8];
    const float* tp_b     = (const float*)d_in[9];
    const float* ln_g     = (const float*)d_in[10];
    const float* ln_b     = (const float*)d_in[11];

    float *Q, *K, *V, *tb, *sc, *ctx, *x;
    cudaGetSymbolAddress((void**)&Q,   g_Q);
    cudaGetSymbolAddress((void**)&K,   g_K);
    cudaGetSymbolAddress((void**)&V,   g_V);
    cudaGetSymbolAddress((void**)&tb,  g_tb);
    cudaGetSymbolAddress((void**)&sc,  g_scores);
    cudaGetSymbolAddress((void**)&ctx, g_ctx);
    cudaGetSymbolAddress((void**)&x,   g_x);

    // 1. time bias (H x S)
    time_bias_kernel<<<S, 512>>>(time_emb, tp_w, tp_b, tb);

    // 2. Q, K, V projections
    dim3 g16(E / BN, L / BM, 1);
    mma_gemm<true><<<g16, 256>>>(query, in_w,             Q, E, E, E, E, 0, 0, 0,
                                 in_b,       0, nullptr, 0, 1.0f);
    mma_gemm<true><<<g16, 256>>>(key,   in_w + (long)E*E, K, E, E, E, E, 0, 0, 0,
                                 in_b + E,   0, nullptr, 0, 1.0f);
    mma_gemm<true><<<g16, 256>>>(value, in_w + 2L*E*E,    V, E, E, E, E, 0, 0, 0,
                                 in_b + 2*E, 0, nullptr, 0, 1.0f);

    // 3. scores[h] = scale * Q_h K_h^T + tb[h]   (K dim = 128 = 4 stages)
    dim3 gsc(S / BN, L / BM, H);
    mma_gemm<true><<<gsc, 256>>>(Q, K, sc, D, E, E, S,
                                 (long)D, (long)D, (long)L * S,
                                 tb, (long)S, nullptr, 0, SCALE);

    // 4. softmax rows
    softmax_rows<<<H * L, 256>>>(sc);

    // 5. ctx[h] = P_h @ V_h   (M=L, N=D, K=S), NN
    dim3 gctx(D / BN, L / BM, H);
    mma_gemm<false><<<gctx, 256>>>(sc, V, ctx, S, S, E, E,
                                   (long)L * S, (long)D, (long)D,
                                   nullptr, 0, nullptr, 0, 1.0f);

    // 6. out projection + residual
    mma_gemm<true><<<g16, 256>>>(ctx, out_w, x, E, E, E, E, 0, 0, 0,
                                 out_b, 0, query, E, 1.0f);

    // 7. LayerNorm -> d_out
    layernorm_kernel<<<L, 256>>>(x, ln_g, ln_b, (float*)d_out);
}

// round 4
// speedup vs baseline: 5.3060x; 1.9785x over previous
#include <cuda_runtime.h>
#include <cuda_bf16.h>
#include <math.h>
#include <stdint.h>

// Problem constants
#define L 2048
#define S 2048
#define E 2048
#define H 16
#define D 128
#define SCALE 0.08838834764831843f  // 1/sqrt(128)

typedef __nv_bfloat16 bf16;

// ---------------- scratch (static device globals; no allocation) -------------
__device__ bf16  g_qin[(long)L * E];
__device__ bf16  g_kin[(long)S * E];
__device__ bf16  g_vin[(long)S * E];
__device__ bf16  g_wb[3L * E * E];
__device__ bf16  g_owb[(long)E * E];
__device__ bf16  g_Qb[(long)L * E];
__device__ bf16  g_Kb[(long)S * E];
__device__ bf16  g_Vb[(long)S * E];
__device__ bf16  g_P[(long)H * L * S];       // softmax probs (bf16)
__device__ bf16  g_ctxb[(long)L * E];
__device__ float g_tb[H * S];
__device__ float g_scores[(long)H * L * S];  // fp32 logits
__device__ float g_x[(long)L * E];

// ---------------- ptx helpers ------------------------------------------------
__device__ __forceinline__ uint32_t pack_bf16(float x, float y) {
    uint32_t u;
    asm("cvt.rn.bf16x2.f32 %0, %1, %2;" : "=r"(u) : "f"(y), "f"(x));
    return u;
}

__device__ __forceinline__ void mma_bf16(float c[4],
                                         uint32_t a0, uint32_t a1, uint32_t a2, uint32_t a3,
                                         uint32_t b0, uint32_t b1) {
    asm volatile(
        "mma.sync.aligned.m16n8k16.row.col.f32.bf16.bf16.f32 "
        "{%0,%1,%2,%3}, {%4,%5,%6,%7}, {%8,%9}, {%0,%1,%2,%3};\n"
        : "+f"(c[0]), "+f"(c[1]), "+f"(c[2]), "+f"(c[3])
        : "r"(a0), "r"(a1), "r"(a2), "r"(a3), "r"(b0), "r"(b1));
}

__device__ __forceinline__ void cp16(uint32_t dst, const void* src) {
    asm volatile("cp.async.cg.shared.global [%0], [%1], 16;" :: "r"(dst), "l"(src));
}
#define CP_COMMIT() asm volatile("cp.async.commit_group;")
#define CP_WAIT1()  asm volatile("cp.async.wait_group 1;")

#define LDSM4(r0, r1, r2, r3, addr)                                            \
    asm volatile("ldmatrix.sync.aligned.m8n8.x4.shared.b16 {%0,%1,%2,%3}, [%4];" \
                 : "=r"(r0), "=r"(r1), "=r"(r2), "=r"(r3) : "r"(addr))
#define LDSM4T(r0, r1, r2, r3, addr)                                           \
    asm volatile("ldmatrix.sync.aligned.m8n8.x4.trans.shared.b16 {%0,%1,%2,%3}, [%4];" \
                 : "=r"(r0), "=r"(r1), "=r"(r2), "=r"(r3) : "r"(addr))

__device__ __forceinline__ float warpReduceSum(float v) {
    #pragma unroll
    for (int o = 16; o > 0; o >>= 1) v += __shfl_xor_sync(0xffffffffu, v, o);
    return v;
}
__device__ __forceinline__ float warpReduceMax(float v) {
    #pragma unroll
    for (int o = 16; o > 0; o >>= 1) v = fmaxf(v, __shfl_xor_sync(0xffffffffu, v, o));
    return v;
}
template<bool MAX>
__device__ __forceinline__ float blockReduce256(float v) {
    __shared__ float sh[8];
    int lane = threadIdx.x & 31, wid = threadIdx.x >> 5;
    v = MAX ? warpReduceMax(v) : warpReduceSum(v);
    if (lane == 0) sh[wid] = v;
    __syncthreads();
    if (wid == 0) {
        float t = (lane < 8) ? sh[lane] : (MAX ? -INFINITY : 0.0f);
        t = MAX ? warpReduceMax(t) : warpReduceSum(t);
        if (lane == 0) sh[0] = t;
    }
    __syncthreads();
    float r = sh[0];
    __syncthreads();
    return r;
}

// ---------------- fp32 -> bf16 conversion ------------------------------------
__global__ __launch_bounds__(256) void cvt_f32_bf16(
    const float4* __restrict__ in, uint2* __restrict__ out, int n4)
{
    int i = blockIdx.x * blockDim.x + threadIdx.x;
    if (i < n4) {
        float4 v = in[i];
        out[i] = make_uint2(pack_bf16(v.x, v.y), pack_bf16(v.z, v.w));
    }
}

// ---------------- bf16 tensor-core GEMM (cp.async + ldmatrix) ----------------
// C[m,n] = scale * sum_k A[m,k] * B'[n,k] + bias[n] (+res[m,n])
//   BT=true : B'[n,k] = B[n*ldb + k]   (NT)
//   BT=false: B'[n,k] = B[k*ldb + n]   (NN)
// Tile 128x128x32, 256 thr (8 warps, warp tile 64x32), mma m16n8k16,
// 3-stage cp.async pipeline, XOR-swizzled smem, ldmatrix fragments.
#define BM 128
#define BN 128
#define BKq 32
#define STAGE_BYTES 16384   // 8KB A + 8KB B

template<bool BT>
__global__ __launch_bounds__(256, 2) void bgemm(
    const bf16* __restrict__ A, const bf16* __restrict__ B,
    float* __restrict__ C, bf16* __restrict__ Cb,
    int K, int lda, int ldb, int ldc,
    long aZ, long bZ, long cZ,
    const float* __restrict__ bias, long biasZ,
    const float* __restrict__ res, int ldr,
    float scale)
{
    const int z = blockIdx.z;
    A += (long)z * aZ;
    B += (long)z * bZ;
    if (C)  C  += (long)z * cZ;
    if (Cb) Cb += (long)z * cZ;
    if (bias) bias += (long)z * biasZ;

    __shared__ __align__(16) unsigned char sm[3 * STAGE_BYTES];
    const uint32_t smBase = (uint32_t)__cvta_generic_to_shared(sm);

    const int tid  = threadIdx.x;
    const int wid  = tid >> 5;
    const int lane = tid & 31;
    const int wm = (wid & 1) * 64;
    const int wn = (wid >> 1) * 32;

    const long m0g = (long)blockIdx.y * BM;
    const long n0g = (long)blockIdx.x * BN;

    // ---- cp.async per-thread assignments ----
    const int rowA = tid >> 2;            // 0..63
    const int cA   = tid & 3;
    const uint32_t aOff = rowA * 64 + ((cA ^ ((rowA >> 1) & 3)) * 16);
    const bf16* gA0 = A + (m0g + rowA) * lda + cA * 8;
    const bf16* gA1 = gA0 + 64 * (long)lda;

    // NT B loader (same pattern as A)
    const bf16* gB0nt = B + (n0g + rowA) * (long)ldb + cA * 8;
    const bf16* gB1nt = gB0nt + 64 * (long)ldb;
    // NN B loader: 32 k-rows x 128 n
    const int rowB = tid >> 4;            // 0..15
    const int cB   = tid & 15;
    const uint32_t bOffN = rowB * 256 + ((cB ^ (rowB & 7)) * 16);
    const bf16* gB0nn = B + (long)rowB * ldb + n0g + cB * 8;
    const bf16* gB1nn = gB0nn + 16 * (long)ldb;

    auto ldg = [&](int st, int k0) {
        uint32_t aSt = smBase + st * STAGE_BYTES;
        uint32_t bSt = aSt + 8192;
        cp16(aSt + aOff,        gA0 + k0);
        cp16(aSt + aOff + 4096, gA1 + k0);
        if (BT) {
            cp16(bSt + aOff,        gB0nt + k0);
            cp16(bSt + aOff + 4096, gB1nt + k0);
        } else {
            cp16(bSt + bOffN,        gB0nn + (long)k0 * ldb);
            cp16(bSt + bOffN + 4096, gB1nn + (long)k0 * ldb);
        }
    };

    // ---- ldmatrix per-lane addressing ----
    const int q = lane >> 3, r = lane & 7;
    // A: rows = wm + mt*16 + (q&1)*8 + r ; chunk = ks*2 + (q>>1)
    const int aRowBase = wm + ((q & 1) << 3) + r;
    const int pa = (aRowBase >> 1) & 3;
    // B NT: rows n = wn + ntp*16 + (q>>1)*8 + r ; chunk = ks*2 + (q&1)
    const int bRowBase = wn + ((q >> 1) << 3) + r;
    const int pb = (bRowBase >> 1) & 3;
    // B NN: k_row = ks*16 + (q&1)*8 + r ; n-chunk cn = (wn>>3) + ntp*2 + (q>>1)
    const int kRowBase = ((q & 1) << 3) + r;
    const int cnBase = (wn >> 3) + (q >> 1);

    float acc[4][4][4];
    #pragma unroll
    for (int i = 0; i < 4; i++)
        #pragma unroll
        for (int j = 0; j < 4; j++)
            #pragma unroll
            for (int t = 0; t < 4; t++) acc[i][j][t] = 0.0f;

    auto compute = [&](int st) {
        uint32_t aSt = smBase + st * STAGE_BYTES;
        uint32_t bSt = aSt + 8192;
        #pragma unroll
        for (int ks = 0; ks < 2; ks++) {
            uint32_t a[4][4];
            #pragma unroll
            for (int mt = 0; mt < 4; mt++) {
                uint32_t addr = aSt + (aRowBase + mt * 16) * 64 +
                                (((ks * 2 + (q >> 1)) ^ pa) * 16);
                LDSM4(a[mt][0], a[mt][1], a[mt][2], a[mt][3], addr);
            }
            uint32_t b[4][2];
            #pragma unroll
            for (int ntp = 0; ntp < 2; ntp++) {
                if (BT) {
                    uint32_t addr = bSt + (bRowBase + ntp * 16) * 64 +
                                    (((ks * 2 + (q & 1)) ^ pb) * 16);
                    LDSM4(b[2*ntp][0], b[2*ntp][1], b[2*ntp+1][0], b[2*ntp+1][1], addr);
                } else {
                    uint32_t addr = bSt + (kRowBase + ks * 16) * 256 +
                                    (((cnBase + ntp * 2) ^ r) * 16);
                    LDSM4T(b[2*ntp][0], b[2*ntp][1], b[2*ntp+1][0], b[2*ntp+1][1], addr);
                }
            }
            #pragma unroll
            for (int mt = 0; mt < 4; mt++)
                #pragma unroll
                for (int nt = 0; nt < 4; nt++)
                    mma_bf16(acc[mt][nt], a[mt][0], a[mt][1], a[mt][2], a[mt][3],
                             b[nt][0], b[nt][1]);
        }
    };

    // ---- pipelined main loop (3 stages) ----
    const int nS = K / BKq;
    ldg(0, 0);       CP_COMMIT();
    ldg(1, BKq);     CP_COMMIT();
    for (int it = 0; it < nS; it++) {
        CP_WAIT1();
        __syncthreads();
        if (it + 2 < nS) { ldg((it + 2) % 3, (it + 2) * BKq); CP_COMMIT(); }
        compute(it % 3);
    }

    // ---- epilogue ----
    const int g = lane >> 2, tig = lane & 3;
    #pragma unroll
    for (int mt = 0; mt < 4; mt++) {
        long r0 = m0g + wm + mt * 16 + g;
        long r1 = r0 + 8;
        #pragma unroll
        for (int nt = 0; nt < 4; nt++) {
            long c = n0g + wn + nt * 8 + 2 * tig;
            float v0 = acc[mt][nt][0] * scale;
            float v1 = acc[mt][nt][1] * scale;
            float v2 = acc[mt][nt][2] * scale;
            float v3 = acc[mt][nt][3] * scale;
            if (bias) {
                float b0 = bias[c], b1 = bias[c + 1];
                v0 += b0; v1 += b1; v2 += b0; v3 += b1;
            }
            if (res) {
                v0 += res[r0 * ldr + c];
                v1 += res[r0 * ldr + c + 1];
                v2 += res[r1 * ldr + c];
                v3 += res[r1 * ldr + c + 1];
            }
            if (C) {
                *(float2*)(C + r0 * ldc + c) = make_float2(v0, v1);
                *(float2*)(C + r1 * ldc + c) = make_float2(v2, v3);
            }
            if (Cb) {
                *(uint32_t*)(Cb + r0 * ldc + c) = pack_bf16(v0, v1);
                *(uint32_t*)(Cb + r1 * ldc + c) = pack_bf16(v2, v3);
            }
        }
    }
}

// ---------------- time bias --------------------------------------------------
__global__ __launch_bounds__(512) void time_bias_kernel(
    const float* __restrict__ te, const float* __restrict__ tpw,
    const float* __restrict__ tpb, float* __restrict__ tb)
{
    int s = blockIdx.x;
    int w = threadIdx.x >> 5, lane = threadIdx.x & 31;
    const float4* rr   = (const float4*)(te  + (long)s * E);
    const float4* wrow = (const float4*)(tpw + (long)w * E);
    float acc = 0.0f;
    for (int e = lane; e < E / 4; e += 32) {
        float4 a = rr[e], b = wrow[e];
        acc += a.x * b.x + a.y * b.y + a.z * b.z + a.w * b.w;
    }
    acc = warpReduceSum(acc);
    if (lane == 0) tb[w * S + s] = acc + tpb[w];
}

// ---------------- softmax: fp32 logits -> bf16 probs -------------------------
__global__ __launch_bounds__(256) void softmax_rows(
    const float* __restrict__ sc, bf16* __restrict__ P)
{
    const float2* p2 = (const float2*)(sc + (long)blockIdx.x * S);
    uint32_t* o = (uint32_t*)(P + (long)blockIdx.x * S);
    int tid = threadIdx.x;
    float2 v[4];
    float mx = -INFINITY;
    #pragma unroll
    for (int i = 0; i < 4; i++) {
        v[i] = p2[tid + i * 256];
        mx = fmaxf(mx, fmaxf(v[i].x, v[i].y));
    }
    mx = blockReduce256<true>(mx);
    float sum = 0.0f;
    #pragma unroll
    for (int i = 0; i < 4; i++) {
        v[i].x = __expf(v[i].x - mx);
        v[i].y = __expf(v[i].y - mx);
        sum += v[i].x + v[i].y;
    }
    sum = blockReduce256<false>(sum);
    float inv = 1.0f / sum;
    #pragma unroll
    for (int i = 0; i < 4; i++)
        o[tid + i * 256] = pack_bf16(v[i].x * inv, v[i].y * inv);
}

// ---------------- LayerNorm --------------------------------------------------
__global__ __launch_bounds__(256) void layernorm_kernel(
    const float* __restrict__ x, const float* __restrict__ g,
    const float* __restrict__ b, float* __restrict__ out)
{
    const float* xr = x + (long)blockIdx.x * E;
    float*       yr = out + (long)blockIdx.x * E;
    int tid = threadIdx.x;
    float vals[8];
    float s = 0.0f, s2 = 0.0f;
    #pragma unroll
    for (int i = 0; i < 8; i++) {
        float v = xr[tid + i * 256];
        vals[i] = v;
        s += v;
        s2 += v * v;
    }
    s  = blockReduce256<false>(s);
    s2 = blockReduce256<false>(s2);
    float mean = s * (1.0f / E);
    float var  = s2 * (1.0f / E) - mean * mean;
    float rstd = rsqrtf(var + 1e-5f);
    #pragma unroll
    for (int i = 0; i < 8; i++) {
        int c = tid + i * 256;
        yr[c] = (vals[i] - mean) * rstd * g[c] + b[c];
    }
}

// ---------------- launch -----------------------------------------------------
extern "C" void kernel_launch(void* const* d_in, const int* in_sizes, int n_in,
                              void* d_out, int out_size)
{
    const float* query    = (const float*)d_in[0];
    const float* key      = (const float*)d_in[1];
    const float* value    = (const float*)d_in[2];
    const float* time_emb = (const float*)d_in[3];
    const float* in_w     = (const float*)d_in[4];
    const float* in_b     = (const float*)d_in[5];
    const float* out_w    = (const float*)d_in[6];
    const float* out_b    = (const float*)d_in[7];
    const float* tp_w     = (const float*)d_in[8];
    const float* tp_b     = (const float*)d_in[9];
    const float* ln_g     = (const float*)d_in[10];
    const float* ln_b     = (const float*)d_in[11];

    bf16 *qin, *kin, *vin, *wb, *owb, *Qb, *Kb, *Vb, *P, *ctxb;
    float *tb, *sc, *x;
    cudaGetSymbolAddress((void**)&qin,  g_qin);
    cudaGetSymbolAddress((void**)&kin,  g_kin);
    cudaGetSymbolAddress((void**)&vin,  g_vin);
    cudaGetSymbolAddress((void**)&wb,   g_wb);
    cudaGetSymbolAddress((void**)&owb,  g_owb);
    cudaGetSymbolAddress((void**)&Qb,   g_Qb);
    cudaGetSymbolAddress((void**)&Kb,   g_Kb);
    cudaGetSymbolAddress((void**)&Vb,   g_Vb);
    cudaGetSymbolAddress((void**)&P,    g_P);
    cudaGetSymbolAddress((void**)&ctxb, g_ctxb);
    cudaGetSymbolAddress((void**)&tb,   g_tb);
    cudaGetSymbolAddress((void**)&sc,   g_scores);
    cudaGetSymbolAddress((void**)&x,    g_x);

    // 0. one-time fp32 -> bf16 conversions
    const int n4a = (L * E) / 4;          // 1,048,576
    const int n4w = (3 * E * E) / 4;      // 3,145,728
    const int n4o = (E * E) / 4;          // 1,048,576
    cvt_f32_bf16<<<(n4a + 255) / 256, 256>>>((const float4*)query, (uint2*)qin, n4a);
    cvt_f32_bf16<<<(n4a + 255) / 256, 256>>>((const float4*)key,   (uint2*)kin, n4a);
    cvt_f32_bf16<<<(n4a + 255) / 256, 256>>>((const float4*)value, (uint2*)vin, n4a);
    cvt_f32_bf16<<<(n4w + 255) / 256, 256>>>((const float4*)in_w,  (uint2*)wb,  n4w);
    cvt_f32_bf16<<<(n4o + 255) / 256, 256>>>((const float4*)out_w, (uint2*)owb, n4o);

    // 1. time bias (H x S)
    time_bias_kernel<<<S, 512>>>(time_emb, tp_w, tp_b, tb);

    // 2. Q, K, V projections (bf16 out)
    dim3 g16(E / BN, L / BM, 1);
    bgemm<true><<<g16, 256>>>(qin, wb,                Qb ? nullptr : nullptr, Qb,
                              E, E, E, E, 0, 0, 0, in_b,       0, nullptr, 0, 1.0f);
    bgemm<true><<<g16, 256>>>(kin, wb + (long)E * E,  nullptr, Kb,
                              E, E, E, E, 0, 0, 0, in_b + E,   0, nullptr, 0, 1.0f);
    bgemm<true><<<g16, 256>>>(vin, wb + 2L * E * E,   nullptr, Vb,
                              E, E, E, E, 0, 0, 0, in_b + 2*E, 0, nullptr, 0, 1.0f);

    // 3. scores[h] = scale * Q_h K_h^T + tb[h]  (fp32 out)
    dim3 gsc(S / BN, L / BM, H);
    bgemm<true><<<gsc, 256>>>(Qb, Kb, sc, nullptr,
                              D, E, E, S, (long)D, (long)D, (long)L * S,
                              tb, (long)S, nullptr, 0, SCALE);

    // 4. softmax -> bf16 probs
    softmax_rows<<<H * L, 256>>>(sc, P);

    // 5. ctx[h] = P_h @ V_h  (NN, bf16 out)
    dim3 gctx(D / BN, L / BM, H);
    bgemm<false><<<gctx, 256>>>(P, Vb, nullptr, ctxb,
                                S, S, E, E, (long)L * S, (long)D, (long)D,
                                nullptr, 0, nullptr, 0, 1.0f);

    // 6. out projection + residual (fp32 out)
    bgemm<true><<<g16, 256>>>(ctxb, owb, x, nullptr,
                              E, E, E, E, 0, 0, 0,
                              out_b, 0, query, E, 1.0f);

    // 7. LayerNorm -> d_out
    layernorm_kernel<<<L, 256>>>(x, ln_g, ln_b, (float*)d_out);
}

// round 6
// speedup vs baseline: 5.6523x; 1.0653x over previous
#include <cuda_runtime.h>
#include <cuda_bf16.h>
#include <math.h>
#include <stdint.h>

// Problem constants
#define L 2048
#define S 2048
#define E 2048
#define H 16
#define D 128
#define SCALE 0.08838834764831843f  // 1/sqrt(128)

typedef __nv_bfloat16 bf16;

// ---------------- scratch (static device globals; no allocation) -------------
__device__ bf16  g_in3[3L * L * E];          // q,k,v inputs (bf16), stacked
__device__ bf16  g_wb[3L * E * E];           // in_proj weights bf16
__device__ bf16  g_owb[(long)E * E];         // out_proj weights bf16
__device__ bf16  g_QKV[3L * L * E];          // Q | K | V (each [L,E])
__device__ bf16  g_ctxb[(long)L * E];
__device__ float g_tb[H * S];
__device__ float g_x[(long)L * E];

// ---------------- ptx helpers ------------------------------------------------
__device__ __forceinline__ uint32_t pack_bf16(float x, float y) {
    uint32_t u;
    asm("cvt.rn.bf16x2.f32 %0, %1, %2;" : "=r"(u) : "f"(y), "f"(x));
    return u;
}

__device__ __forceinline__ void mma_bf16(float c[4],
                                         uint32_t a0, uint32_t a1, uint32_t a2, uint32_t a3,
                                         uint32_t b0, uint32_t b1) {
    asm volatile(
        "mma.sync.aligned.m16n8k16.row.col.f32.bf16.bf16.f32 "
        "{%0,%1,%2,%3}, {%4,%5,%6,%7}, {%8,%9}, {%0,%1,%2,%3};\n"
        : "+f"(c[0]), "+f"(c[1]), "+f"(c[2]), "+f"(c[3])
        : "r"(a0), "r"(a1), "r"(a2), "r"(a3), "r"(b0), "r"(b1));
}

__device__ __forceinline__ void cp16(uint32_t dst, const void* src) {
    asm volatile("cp.async.cg.shared.global [%0], [%1], 16;" :: "r"(dst), "l"(src));
}
#define CP_COMMIT() asm volatile("cp.async.commit_group;")
#define CP_WAIT1()  asm volatile("cp.async.wait_group 1;")
#define CP_WAIT0()  asm volatile("cp.async.wait_group 0;")

#define LDSM4(r0, r1, r2, r3, addr)                                            \
    asm volatile("ldmatrix.sync.aligned.m8n8.x4.shared.b16 {%0,%1,%2,%3}, [%4];" \
                 : "=r"(r0), "=r"(r1), "=r"(r2), "=r"(r3) : "r"(addr))
#define LDSM4T(r0, r1, r2, r3, addr)                                           \
    asm volatile("ldmatrix.sync.aligned.m8n8.x4.trans.shared.b16 {%0,%1,%2,%3}, [%4];" \
                 : "=r"(r0), "=r"(r1), "=r"(r2), "=r"(r3) : "r"(addr))

__device__ __forceinline__ float warpReduceSum(float v) {
    #pragma unroll
    for (int o = 16; o > 0; o >>= 1) v += __shfl_xor_sync(0xffffffffu, v, o);
    return v;
}
template<bool MAX>
__device__ __forceinline__ float blockReduce256(float v) {
    __shared__ float sh[8];
    int lane = threadIdx.x & 31, wid = threadIdx.x >> 5;
    #pragma unroll
    for (int o = 16; o > 0; o >>= 1)
        v = MAX ? fmaxf(v, __shfl_xor_sync(0xffffffffu, v, o))
                : v + __shfl_xor_sync(0xffffffffu, v, o);
    if (lane == 0) sh[wid] = v;
    __syncthreads();
    if (wid == 0) {
        float t = (lane < 8) ? sh[lane] : (MAX ? -INFINITY : 0.0f);
        #pragma unroll
        for (int o = 4; o > 0; o >>= 1)
            t = MAX ? fmaxf(t, __shfl_xor_sync(0xffffffffu, t, o))
                    : t + __shfl_xor_sync(0xffffffffu, t, o);
        if (lane == 0) sh[0] = t;
    }
    __syncthreads();
    float r = sh[0];
    __syncthreads();
    return r;
}

// ---------------- fp32 -> bf16 conversion ------------------------------------
__global__ __launch_bounds__(256) void cvt_f32_bf16(
    const float4* __restrict__ in, uint2* __restrict__ out, int n4)
{
    int i = blockIdx.x * blockDim.x + threadIdx.x;
    if (i < n4) {
        float4 v = in[i];
        out[i] = make_uint2(pack_bf16(v.x, v.y), pack_bf16(v.z, v.w));
    }
}

// ================= mma.sync NT GEMM (projections) ============================
#define BM 128
#define BN 128
#define BKq 32
#define STAGE_BYTES 16384

__global__ __launch_bounds__(256, 2) void bgemm_nt(
    const bf16* __restrict__ A, const bf16* __restrict__ B,
    float* __restrict__ C, bf16* __restrict__ Cb,
    int K, int lda, int ldb, int ldc,
    long aZ, long bZ, long cZ,
    const float* __restrict__ bias, long biasZ,
    const float* __restrict__ res, int ldr,
    float scale)
{
    const int z = blockIdx.z;
    A += (long)z * aZ;
    B += (long)z * bZ;
    if (C)  C  += (long)z * cZ;
    if (Cb) Cb += (long)z * cZ;
    if (bias) bias += (long)z * biasZ;

    __shared__ __align__(16) unsigned char sm[3 * STAGE_BYTES];
    const uint32_t smBase = (uint32_t)__cvta_generic_to_shared(sm);

    const int tid  = threadIdx.x;
    const int wid  = tid >> 5;
    const int lane = tid & 31;
    const int wm = (wid & 1) * 64;
    const int wn = (wid >> 1) * 32;

    const long m0g = (long)blockIdx.y * BM;
    const long n0g = (long)blockIdx.x * BN;

    const int rowA = tid >> 2;
    const int cA   = tid & 3;
    const uint32_t aOff = rowA * 64 + ((cA ^ ((rowA >> 1) & 3)) * 16);
    const bf16* gA0 = A + (m0g + rowA) * (long)lda + cA * 8;
    const bf16* gA1 = gA0 + 64 * (long)lda;
    const bf16* gB0 = B + (n0g + rowA) * (long)ldb + cA * 8;
    const bf16* gB1 = gB0 + 64 * (long)ldb;

    auto ldg = [&](int st, int k0) {
        uint32_t aSt = smBase + st * STAGE_BYTES;
        uint32_t bSt = aSt + 8192;
        cp16(aSt + aOff,        gA0 + k0);
        cp16(aSt + aOff + 4096, gA1 + k0);
        cp16(bSt + aOff,        gB0 + k0);
        cp16(bSt + aOff + 4096, gB1 + k0);
        CP_COMMIT();
    };

    const int q = lane >> 3, r = lane & 7;
    const int aRowBase = wm + ((q & 1) << 3) + r;
    const int pa = (aRowBase >> 1) & 3;
    const int bRowBase = wn + ((q >> 1) << 3) + r;
    const int pb = (bRowBase >> 1) & 3;

    float acc[4][4][4];
    #pragma unroll
    for (int i = 0; i < 4; i++)
        #pragma unroll
        for (int j = 0; j < 4; j++)
            #pragma unroll
            for (int t = 0; t < 4; t++) acc[i][j][t] = 0.0f;

    auto compute = [&](int st) {
        uint32_t aSt = smBase + st * STAGE_BYTES;
        uint32_t bSt = aSt + 8192;
        #pragma unroll
        for (int ks = 0; ks < 2; ks++) {
            uint32_t a[4][4];
            #pragma unroll
            for (int mt = 0; mt < 4; mt++) {
                uint32_t addr = aSt + (aRowBase + mt * 16) * 64 +
                                (((ks * 2 + (q >> 1)) ^ pa) * 16);
                LDSM4(a[mt][0], a[mt][1], a[mt][2], a[mt][3], addr);
            }
            uint32_t b[4][2];
            #pragma unroll
            for (int ntp = 0; ntp < 2; ntp++) {
                uint32_t addr = bSt + (bRowBase + ntp * 16) * 64 +
                                (((ks * 2 + (q & 1)) ^ pb) * 16);
                LDSM4(b[2*ntp][0], b[2*ntp][1], b[2*ntp+1][0], b[2*ntp+1][1], addr);
            }
            #pragma unroll
            for (int mt = 0; mt < 4; mt++)
                #pragma unroll
                for (int nt = 0; nt < 4; nt++)
                    mma_bf16(acc[mt][nt], a[mt][0], a[mt][1], a[mt][2], a[mt][3],
                             b[nt][0], b[nt][1]);
        }
    };

    const int nS = K / BKq;
    ldg(0, 0);
    ldg(1, BKq);
    for (int it = 0; it < nS; it++) {
        CP_WAIT1();
        __syncthreads();
        if (it + 2 < nS) ldg((it + 2) % 3, (it + 2) * BKq);
        compute(it % 3);
    }

    const int g = lane >> 2, tig = lane & 3;
    #pragma unroll
    for (int mt = 0; mt < 4; mt++) {
        long r0 = m0g + wm + mt * 16 + g;
        long r1 = r0 + 8;
        #pragma unroll
        for (int nt = 0; nt < 4; nt++) {
            long c = n0g + wn + nt * 8 + 2 * tig;
            float v0 = acc[mt][nt][0] * scale;
            float v1 = acc[mt][nt][1] * scale;
            float v2 = acc[mt][nt][2] * scale;
            float v3 = acc[mt][nt][3] * scale;
            if (bias) {
                float b0 = bias[c], b1 = bias[c + 1];
                v0 += b0; v1 += b1; v2 += b0; v3 += b1;
            }
            if (res) {
                v0 += res[r0 * ldr + c];
                v1 += res[r0 * ldr + c + 1];
                v2 += res[r1 * ldr + c];
                v3 += res[r1 * ldr + c + 1];
            }
            if (C) {
                *(float2*)(C + r0 * ldc + c) = make_float2(v0, v1);
                *(float2*)(C + r1 * ldc + c) = make_float2(v2, v3);
            }
            if (Cb) {
                *(uint32_t*)(Cb + r0 * ldc + c) = pack_bf16(v0, v1);
                *(uint32_t*)(Cb + r1 * ldc + c) = pack_bf16(v2, v3);
            }
        }
    }
}

// ================= fused flash attention =====================================
// grid (L/128, H), 256 threads (8 warps, 16 q-rows per warp).
// smem: Q 32KB | K0 16K | V0 16K | K1 16K | V1 16K | tb 8KB = 104KB
#define FA_SMEM (32768 + 4 * 16384 + 8192)
#define NCHUNK (S / 64)

__global__ __launch_bounds__(256, 2) void flash_attn(
    const bf16* __restrict__ Qg, const bf16* __restrict__ Kg,
    const bf16* __restrict__ Vg, const float* __restrict__ tbg,
    bf16* __restrict__ ctx)
{
    extern __shared__ __align__(128) unsigned char fsm[];
    const uint32_t sb = (uint32_t)__cvta_generic_to_shared(fsm);
    const uint32_t qB  = sb;
    const uint32_t tbB = sb + 98304;
    float* tbS = (float*)(fsm + 98304);

    const int tid = threadIdx.x;
    const int w = tid >> 5, lane = tid & 31;
    const int q = lane >> 3, r = lane & 7;
    const int g = lane >> 2, tig = lane & 3;
    const int m0 = blockIdx.x * 128;
    const int h  = blockIdx.y;

    const bf16* Qp = Qg + h * D;
    const bf16* Kp = Kg + h * D;
    const bf16* Vp = Vg + h * D;
    const float* tbh = tbg + h * S;

    // ---- load Q tile + tb row (with chunk 0 in group 0) ----
    {
        int row = tid >> 1, half = tid & 1;
        const bf16* src = Qp + (long)(m0 + row) * E + half * 64;
        uint32_t dst = qB + row * 256;
        #pragma unroll
        for (int c = 0; c < 8; c++) {
            int ch = half * 8 + c;
            cp16(dst + ((ch ^ (row & 7)) * 16), src + c * 8);
        }
        cp16(tbB + tid * 32,      tbh + tid * 8);
        cp16(tbB + tid * 32 + 16, tbh + tid * 8 + 4);
    }

    auto ldkv = [&](int buf, int j) {
        uint32_t base = sb + 32768 + buf * 32768;
        const int half = tid & 1;
        int row  = (tid & 127) >> 1;
        const bf16* src = (tid < 128)
            ? (Kp + (long)(j * 64 + row) * E + half * 64)
            : (Vp + (long)(j * 64 + row) * E + half * 64);
        uint32_t dst = base + (tid < 128 ? 0 : 16384) + row * 256;
        #pragma unroll
        for (int c = 0; c < 8; c++) {
            int ch = half * 8 + c;
            cp16(dst + ((ch ^ (row & 7)) * 16), src + c * 8);
        }
    };

    ldkv(0, 0);
    CP_COMMIT();

    float o[16][4];
    #pragma unroll
    for (int i = 0; i < 16; i++)
        #pragma unroll
        for (int t = 0; t < 4; t++) o[i][t] = 0.0f;
    float rmax0 = -INFINITY, rmax1 = -INFINITY;
    float rsum0 = 0.0f, rsum1 = 0.0f;

    const int aRow = w * 16 + ((q & 1) << 3) + r;

    for (int j = 0; j < NCHUNK; j++) {
        const int b = j & 1;
        if (j + 1 < NCHUNK) { ldkv(b ^ 1, j + 1); CP_COMMIT(); CP_WAIT1(); }
        else                { CP_WAIT0(); }
        __syncthreads();
        const uint32_t kBuf = sb + 32768 + b * 32768;
        const uint32_t vBuf = kBuf + 16384;

        // ---- scores: S = Q K^T (128x64 per block, 16x64 per warp) ----
        float sc[8][4];
        #pragma unroll
        for (int nf = 0; nf < 8; nf++)
            #pragma unroll
            for (int t = 0; t < 4; t++) sc[nf][t] = 0.0f;

        #pragma unroll
        for (int kc = 0; kc < 8; kc++) {
            uint32_t a0, a1, a2, a3;
            LDSM4(a0, a1, a2, a3,
                  qB + aRow * 256 + (((2 * kc + (q >> 1)) ^ r) * 16));
            #pragma unroll
            for (int ntg = 0; ntg < 4; ntg++) {
                uint32_t b0, b1, b2, b3;
                int nRow = ntg * 16 + ((q >> 1) << 3) + r;
                LDSM4(b0, b1, b2, b3,
                      kBuf + nRow * 256 + (((2 * kc + (q & 1)) ^ r) * 16));
                mma_bf16(sc[2 * ntg],     a0, a1, a2, a3, b0, b1);
                mma_bf16(sc[2 * ntg + 1], a0, a1, a2, a3, b2, b3);
            }
        }

        // ---- scale + time bias + online softmax ----
        float mxn0 = rmax0, mxn1 = rmax1;
        #pragma unroll
        for (int nf = 0; nf < 8; nf++) {
            int col = j * 64 + nf * 8 + 2 * tig;
            float t0 = tbS[col], t1 = tbS[col + 1];
            sc[nf][0] = fmaf(sc[nf][0], SCALE, t0);
            sc[nf][1] = fmaf(sc[nf][1], SCALE, t1);
            sc[nf][2] = fmaf(sc[nf][2], SCALE, t0);
            sc[nf][3] = fmaf(sc[nf][3], SCALE, t1);
            mxn0 = fmaxf(mxn0, fmaxf(sc[nf][0], sc[nf][1]));
            mxn1 = fmaxf(mxn1, fmaxf(sc[nf][2], sc[nf][3]));
        }
        mxn0 = fmaxf(mxn0, __shfl_xor_sync(0xffffffffu, mxn0, 1));
        mxn0 = fmaxf(mxn0, __shfl_xor_sync(0xffffffffu, mxn0, 2));
        mxn1 = fmaxf(mxn1, __shfl_xor_sync(0xffffffffu, mxn1, 1));
        mxn1 = fmaxf(mxn1, __shfl_xor_sync(0xffffffffu, mxn1, 2));

        float f0 = __expf(rmax0 - mxn0);
        float f1 = __expf(rmax1 - mxn1);
        rmax0 = mxn0; rmax1 = mxn1;

        float ls0 = 0.0f, ls1 = 0.0f;
        #pragma unroll
        for (int nf = 0; nf < 8; nf++) {
            sc[nf][0] = __expf(sc[nf][0] - mxn0);
            sc[nf][1] = __expf(sc[nf][1] - mxn0);
            sc[nf][2] = __expf(sc[nf][2] - mxn1);
            sc[nf][3] = __expf(sc[nf][3] - mxn1);
            ls0 += sc[nf][0] + sc[nf][1];
            ls1 += sc[nf][2] + sc[nf][3];
        }
        ls0 += __shfl_xor_sync(0xffffffffu, ls0, 1);
        ls0 += __shfl_xor_sync(0xffffffffu, ls0, 2);
        ls1 += __shfl_xor_sync(0xffffffffu, ls1, 1);
        ls1 += __shfl_xor_sync(0xffffffffu, ls1, 2);
        rsum0 = rsum0 * f0 + ls0;
        rsum1 = rsum1 * f1 + ls1;

        #pragma unroll
        for (int nf2 = 0; nf2 < 16; nf2++) {
            o[nf2][0] *= f0; o[nf2][1] *= f0;
            o[nf2][2] *= f1; o[nf2][3] *= f1;
        }

        // P frags for the PV mma (no shuffles needed)
        uint32_t pA[4][4];
        #pragma unroll
        for (int kc2 = 0; kc2 < 4; kc2++) {
            pA[kc2][0] = pack_bf16(sc[2 * kc2][0],     sc[2 * kc2][1]);
            pA[kc2][1] = pack_bf16(sc[2 * kc2][2],     sc[2 * kc2][3]);
            pA[kc2][2] = pack_bf16(sc[2 * kc2 + 1][0], sc[2 * kc2 + 1][1]);
            pA[kc2][3] = pack_bf16(sc[2 * kc2 + 1][2], sc[2 * kc2 + 1][3]);
        }

        // ---- O += P V ----
        #pragma unroll
        for (int kc2 = 0; kc2 < 4; kc2++) {
            int kRow = kc2 * 16 + ((q & 1) << 3) + r;
            #pragma unroll
            for (int ntg = 0; ntg < 8; ntg++) {
                uint32_t b0, b1, b2, b3;
                LDSM4T(b0, b1, b2, b3,
                       vBuf + kRow * 256 + ((((ntg << 1) + (q >> 1)) ^ r) * 16));
                mma_bf16(o[2 * ntg],     pA[kc2][0], pA[kc2][1], pA[kc2][2], pA[kc2][3], b0, b1);
                mma_bf16(o[2 * ntg + 1], pA[kc2][0], pA[kc2][1], pA[kc2][2], pA[kc2][3], b2, b3);
            }
        }
        __syncthreads();
    }

    // ---- epilogue: O / rowsum -> ctx (bf16) ----
    float i0 = 1.0f / rsum0, i1 = 1.0f / rsum1;
    long r0 = m0 + w * 16 + g;
    long r1 = r0 + 8;
    bf16* c0 = ctx + r0 * E + h * D;
    bf16* c1 = ctx + r1 * E + h * D;
    #pragma unroll
    for (int nf2 = 0; nf2 < 16; nf2++) {
        int col = nf2 * 8 + 2 * tig;
        *(uint32_t*)(c0 + col) = pack_bf16(o[nf2][0] * i0, o[nf2][1] * i0);
        *(uint32_t*)(c1 + col) = pack_bf16(o[nf2][2] * i1, o[nf2][3] * i1);
    }
}

// ---------------- time bias --------------------------------------------------
__global__ __launch_bounds__(512) void time_bias_kernel(
    const float* __restrict__ te, const float* __restrict__ tpw,
    const float* __restrict__ tpb, float* __restrict__ tb)
{
    int s = blockIdx.x;
    int w = threadIdx.x >> 5, lane = threadIdx.x & 31;
    const float4* rr   = (const float4*)(te  + (long)s * E);
    const float4* wrow = (const float4*)(tpw + (long)w * E);
    float acc = 0.0f;
    for (int e = lane; e < E / 4; e += 32) {
        float4 a = rr[e], b = wrow[e];
        acc += a.x * b.x + a.y * b.y + a.z * b.z + a.w * b.w;
    }
    acc = warpReduceSum(acc);
    if (lane == 0) tb[w * S + s] = acc + tpb[w];
}

// ---------------- LayerNorm --------------------------------------------------
__global__ __launch_bounds__(256) void layernorm_kernel(
    const float* __restrict__ x, const float* __restrict__ g,
    const float* __restrict__ b, float* __restrict__ out)
{
    const float* xr = x + (long)blockIdx.x * E;
    float*       yr = out + (long)blockIdx.x * E;
    int tid = threadIdx.x;
    float vals[8];
    float s = 0.0f, s2 = 0.0f;
    #pragma unroll
    for (int i = 0; i < 8; i++) {
        float v = xr[tid + i * 256];
        vals[i] = v;
        s += v;
        s2 += v * v;
    }
    s  = blockReduce256<false>(s);
    s2 = blockReduce256<false>(s2);
    float mean = s * (1.0f / E);
    float var  = s2 * (1.0f / E) - mean * mean;
    float rstd = rsqrtf(var + 1e-5f);
    #pragma unroll
    for (int i = 0; i < 8; i++) {
        int c = tid + i * 256;
        yr[c] = (vals[i] - mean) * rstd * g[c] + b[c];
    }
}

// ---------------- launch -----------------------------------------------------
extern "C" void kernel_launch(void* const* d_in, const int* in_sizes, int n_in,
                              void* d_out, int out_size)
{
    const float* query    = (const float*)d_in[0];
    const float* key      = (const float*)d_in[1];
    const float* value    = (const float*)d_in[2];
    const float* time_emb = (const float*)d_in[3];
    const float* in_w     = (const float*)d_in[4];
    const float* in_b     = (const float*)d_in[5];
    const float* out_w    = (const float*)d_in[6];
    const float* out_b    = (const float*)d_in[7];
    const float* tp_w     = (const float*)d_in[8];
    const float* tp_b     = (const float*)d_in[9];
    const float* ln_g     = (const float*)d_in[10];
    const float* ln_b     = (const float*)d_in[11];

    bf16 *in3, *wb, *owb, *QKV, *ctxb;
    float *tb, *x;
    cudaGetSymbolAddress((void**)&in3,  g_in3);
    cudaGetSymbolAddress((void**)&wb,   g_wb);
    cudaGetSymbolAddress((void**)&owb,  g_owb);
    cudaGetSymbolAddress((void**)&QKV,  g_QKV);
    cudaGetSymbolAddress((void**)&ctxb, g_ctxb);
    cudaGetSymbolAddress((void**)&tb,   g_tb);
    cudaGetSymbolAddress((void**)&x,    g_x);

    cudaFuncSetAttribute(flash_attn, cudaFuncAttributeMaxDynamicSharedMemorySize, FA_SMEM);

    // 0. one-time fp32 -> bf16 conversions
    const int n4a = (L * E) / 4;
    const int n4w = (3 * E * E) / 4;
    const int n4o = (E * E) / 4;
    cvt_f32_bf16<<<(n4a + 255) / 256, 256>>>((const float4*)query, (uint2*)in3, n4a);
    cvt_f32_bf16<<<(n4a + 255) / 256, 256>>>((const float4*)key,   (uint2*)(in3 + (long)L * E), n4a);
    cvt_f32_bf16<<<(n4a + 255) / 256, 256>>>((const float4*)value, (uint2*)(in3 + 2L * L * E), n4a);
    cvt_f32_bf16<<<(n4w + 255) / 256, 256>>>((const float4*)in_w,  (uint2*)wb,  n4w);
    cvt_f32_bf16<<<(n4o + 255) / 256, 256>>>((const float4*)out_w, (uint2*)owb, n4o);

    // 1. time bias (H x S)
    time_bias_kernel<<<S, 512>>>(time_emb, tp_w, tp_b, tb);

    // 2. Q,K,V projections in one launch (grid.z selects q/k/v)
    bf16* Qb = QKV;
    bf16* Kb = QKV + (long)L * E;
    bf16* Vb = QKV + 2L * L * E;
    dim3 gqkv(E / BN, L / BM, 3);
    bgemm_nt<<<gqkv, 256>>>(in3, wb, nullptr, QKV,
                            E, E, E, E,
                            (long)L * E, (long)E * E, (long)L * E,
                            in_b, (long)E, nullptr, 0, 1.0f);

    // 3-5. fused attention (scores + time bias + softmax + PV)
    dim3 gfa(L / 128, H);
    flash_attn<<<gfa, 256, FA_SMEM>>>(Qb, Kb, Vb, tb, ctxb);

    // 6. out projection + residual (fp32 out)
    dim3 gop(E / BN, L / BM, 1);
    bgemm_nt<<<gop, 256>>>(ctxb, owb, x, nullptr,
                           E, E, E, E, 0, 0, 0,
                           out_b, 0, query, E, 1.0f);

    // 7. LayerNorm -> d_out
    layernorm_kernel<<<L, 256>>>(x, ln_g, ln_b, (float*)d_out);
}